// round 1
// baseline (speedup 1.0000x reference)
#include <cuda_runtime.h>
#include <math.h>

#define BB      16
#define NA      286
#define NPAIR   (NA*NA)
#define HID     150
#define HIDP    160
#define FF      512
#define RADIUS_F 3.0f
#define MT      2048      // table knots per cloud

// ---------------- scratch (device globals; no allocation allowed) ----------
__device__ __align__(16) float g_feats0[BB*NA*4];
__device__ __align__(16) float g_f1[BB*NA*4];
__device__ __align__(16) float g_f2[BB*NA*4];
__device__ float g_dist[BB*NPAIR];
__device__ float g_nbinv[BB*NA];
__device__ __align__(16) float g_tab[2][MT*16];
__device__ float g_wpad[4][HID*HIDP];     // c0_w1, c0_w2, c1_w1, c1_w2 (padded rows of 160)
__device__ float g_pooled[BB*8];
__device__ float g_h[BB*FF];
__device__ float g_mean[FF];
__device__ float g_var[FF];

__device__ __forceinline__ float sp5(float x) {
    float z = 5.0f * x;
    return (fmaxf(z, 0.0f) + log1pf(expf(-fabsf(z)))) * 0.2f;
}
__device__ __forceinline__ float softplus1(float x) {
    return fmaxf(x, 0.0f) + log1pf(expf(-fabsf(x)));
}

// ---------------- 1. embedding gather: feats0[z,n,:] = emb[Z[z,n]] --------
__global__ void k_embed(const int* __restrict__ Z, const float* __restrict__ emb) {
    int i = blockIdx.x * blockDim.x + threadIdx.x;
    if (i < BB*NA) {
        int zi = Z[i];
        float4 e = *(const float4*)(emb + zi*4);
        *(float4*)(g_feats0 + i*4) = e;
    }
}

// ---------------- 2. pad mid-layer weights to 160-wide rows ---------------
__global__ void k_pad(const float* __restrict__ a, const float* __restrict__ b,
                      const float* __restrict__ c, const float* __restrict__ d) {
    const float* srcs[4] = {a, b, c, d};
    int m = blockIdx.y;
    const float* src = srcs[m];
    int i = blockIdx.x * blockDim.x + threadIdx.x;
    if (i < HID*HIDP) {
        int k = i / HIDP;
        int o = i - k*HIDP;
        g_wpad[m][i] = (o < HID) ? src[k*HID + o] : 0.0f;
    }
}

// ---------------- 3. pairwise distances + 1/sqrt(neighbor count) ----------
__global__ void k_dist(const float* __restrict__ xyz) {
    int za = blockIdx.x;
    int z = za / NA, a = za % NA;
    const float* pz = xyz + (size_t)z * NA * 3;
    float ax = pz[a*3+0], ay = pz[a*3+1], az = pz[a*3+2];
    int cnt = 0;
    for (int b = threadIdx.x; b < NA; b += blockDim.x) {
        float dx = ax - pz[b*3+0];
        float dy = ay - pz[b*3+1];
        float dz = az - pz[b*3+2];
        float d = sqrtf(dx*dx + dy*dy + dz*dz + 1e-12f);
        g_dist[(size_t)za*NA + b] = d;
        cnt += (d < RADIUS_F) ? 1 : 0;
    }
    for (int off = 16; off; off >>= 1) cnt += __shfl_down_sync(0xffffffffu, cnt, off);
    __shared__ int sc[8];
    int warp = threadIdx.x >> 5;
    if ((threadIdx.x & 31) == 0) sc[warp] = cnt;
    __syncthreads();
    if (threadIdx.x == 0) {
        int t = 0;
        for (int w = 0; w < (int)(blockDim.x >> 5); w++) t += sc[w];
        g_nbinv[za] = rsqrtf((float)max(t, 1));
    }
}

// ---------------- 4. radial-MLP table build -------------------------------
struct CloudW {
    const float* w0; const float* b0;
    const float* b1; const float* b2;
    const float* w3; const float* b3;
};
struct BuildArgs { CloudW c[2]; };

#define PTW 4   // points per warp
#define BW  8   // warps per block

__global__ void k_build(BuildArgs args) {
    int cloud = blockIdx.y;
    CloudW cw = args.c[cloud];
    int warp = threadIdx.x >> 5, lane = threadIdx.x & 31;
    int pt0 = (blockIdx.x * BW + warp) * PTW;

    __shared__ float sh[2][BW][PTW][HID + 2];
    float (*A)[HID + 2]  = sh[0][warp];
    float (*Bf)[HID + 2] = sh[1][warp];

    // cosine basis at the PTW grid points
    float bas[PTW][3];
    const float hstep = RADIUS_F / (float)(MT - 1);
    #pragma unroll
    for (int p = 0; p < PTW; p++) {
        float r = (float)(pt0 + p) * hstep;
        #pragma unroll
        for (int j = 0; j < 3; j++) {
            float dd = (r - 1.5f * (float)j) * (1.0f / 1.5f);
            float cv = cosf(1.57079632679489662f * dd);
            bas[p][j] = (fabsf(dd) < 1.0f) ? cv * cv : 0.0f;
        }
    }

    // layer 0: 3 -> 150
    #pragma unroll
    for (int it = 0; it < 5; ++it) {
        int o = lane + 32 * it;
        if (o < HID) {
            float w0a = cw.w0[o], w0b = cw.w0[HID + o], w0c = cw.w0[2*HID + o];
            float bb0 = cw.b0[o];
            #pragma unroll
            for (int p = 0; p < PTW; p++) {
                float av = bb0 + bas[p][0]*w0a + bas[p][1]*w0b + bas[p][2]*w0c;
                A[p][o] = sp5(av);
            }
        }
    }
    __syncwarp();

    // layers 1 & 2: 150 -> 150 (padded weights, k-outer register blocking)
    for (int L = 0; L < 2; ++L) {
        const float* wp = g_wpad[2*cloud + L];
        const float* bb = (L == 0) ? cw.b1 : cw.b2;
        float (*S)[HID + 2] = (L == 0) ? A : Bf;
        float (*D)[HID + 2] = (L == 0) ? Bf : A;

        float acc[5][PTW];
        #pragma unroll
        for (int it = 0; it < 5; ++it) {
            int o = lane + 32 * it;
            float bv = (o < HID) ? bb[o] : 0.0f;
            #pragma unroll
            for (int p = 0; p < PTW; p++) acc[it][p] = bv;
        }
        #pragma unroll 2
        for (int k = 0; k < HID; k++) {
            float s[PTW];
            #pragma unroll
            for (int p = 0; p < PTW; p++) s[p] = S[p][k];
            #pragma unroll
            for (int it = 0; it < 5; ++it) {
                float w = wp[k*HIDP + lane + 32*it];
                #pragma unroll
                for (int p = 0; p < PTW; p++) acc[it][p] = fmaf(s[p], w, acc[it][p]);
            }
        }
        #pragma unroll
        for (int it = 0; it < 5; ++it) {
            int o = lane + 32 * it;
            if (o < HID) {
                #pragma unroll
                for (int p = 0; p < PTW; p++) D[p][o] = sp5(acc[it][p]);
            }
        }
        __syncwarp();
    }

    // layer 3: 150 -> 16 (source is A after layer 2)
    if (lane < 16) {
        float acc[PTW];
        #pragma unroll
        for (int p = 0; p < PTW; p++) acc[p] = cw.b3[lane];
        for (int k = 0; k < HID; k++) {
            float w = cw.w3[k*16 + lane];
            #pragma unroll
            for (int p = 0; p < PTW; p++) acc[p] = fmaf(A[p][k], w, acc[p]);
        }
        #pragma unroll
        for (int p = 0; p < PTW; p++)
            g_tab[cloud][(pt0 + p)*16 + lane] = acc[p];
    }
}

// ---------------- 5. pair convolution (table interp + 4x4 matvec) ---------
// 4 lanes per pair; lane q computes output channel q. 8 pairs per warp.
__global__ void k_conv(int cloud) {
    int za = blockIdx.x;
    int z = za / NA;
    const float* feats = (cloud == 0) ? g_feats0 : g_f1;
    float* out         = (cloud == 0) ? g_f1     : g_f2;
    const float* tab   = g_tab[cloud];

    __shared__ float4 sf[NA];
    const float4* fz = (const float4*)(feats + (size_t)z * NA * 4);
    for (int b = threadIdx.x; b < NA; b += blockDim.x) sf[b] = fz[b];
    __syncthreads();

    const float* drow = g_dist + (size_t)za * NA;
    int lane = threadIdx.x & 31, warp = threadIdx.x >> 5;
    int q = lane & 3;        // output channel
    int p = lane >> 2;       // pair slot within warp (0..7)
    const float uscale = (float)(MT - 1) / RADIUS_F;

    float acc = 0.0f;
    for (int b = warp*8 + p; b < NA; b += 64) {
        float r = drow[b];
        if (r < RADIUS_F) {
            float u = r * uscale;
            int i0 = (int)u;
            i0 = min(i0, MT - 2);
            float t = u - (float)i0;
            const float4* rp = (const float4*)(tab + i0*16) + q;
            float4 k0 = rp[0];
            float4 k1 = rp[4];
            float kx = fmaf(t, k1.x - k0.x, k0.x);
            float ky = fmaf(t, k1.y - k0.y, k0.y);
            float kz = fmaf(t, k1.z - k0.z, k0.z);
            float kw = fmaf(t, k1.w - k0.w, k0.w);
            float4 f = sf[b];
            acc += kx*f.x + ky*f.y + kz*f.z + kw*f.w;
        }
    }
    // reduce over pair slots (same q): lanes differing in bits 2..4
    acc += __shfl_down_sync(0xffffffffu, acc, 16);
    acc += __shfl_down_sync(0xffffffffu, acc, 8);
    acc += __shfl_down_sync(0xffffffffu, acc, 4);
    __shared__ float sr[8][4];
    if (lane < 4) sr[warp][q] = acc;
    __syncthreads();
    if (threadIdx.x < 4) {
        float s = 0.0f;
        #pragma unroll
        for (int w = 0; w < 8; w++) s += sr[w][threadIdx.x];
        out[(size_t)za*4 + threadIdx.x] = s * g_nbinv[za];
    }
}

// ---------------- 6. L2 pool over atoms -----------------------------------
__global__ void k_pool() {
    int z = blockIdx.x;
    int lane = threadIdx.x & 31, warp = threadIdx.x >> 5;
    float s[8] = {0,0,0,0,0,0,0,0};
    for (int a = threadIdx.x; a < NA; a += blockDim.x) {
        float4 f1 = *(const float4*)(g_f1 + ((size_t)z*NA + a)*4);
        float4 f2 = *(const float4*)(g_f2 + ((size_t)z*NA + a)*4);
        s[0] += f1.x*f1.x; s[1] += f1.y*f1.y; s[2] += f1.z*f1.z; s[3] += f1.w*f1.w;
        s[4] += f2.x*f2.x; s[5] += f2.y*f2.y; s[6] += f2.z*f2.z; s[7] += f2.w*f2.w;
    }
    #pragma unroll
    for (int j = 0; j < 8; j++)
        for (int off = 16; off; off >>= 1) s[j] += __shfl_down_sync(0xffffffffu, s[j], off);
    __shared__ float sm[8][8];
    if (lane == 0) {
        #pragma unroll
        for (int j = 0; j < 8; j++) sm[warp][j] = s[j];
    }
    __syncthreads();
    if (threadIdx.x < 8) {
        float t = 0.0f;
        #pragma unroll
        for (int w = 0; w < 8; w++) t += sm[w][threadIdx.x];
        g_pooled[z*8 + threadIdx.x] = sqrtf(t);
    }
}

// ---------------- 7. FC + softplus ----------------------------------------
__global__ void k_fc(const float* __restrict__ fcw, const float* __restrict__ fcb) {
    int z = blockIdx.x, f = threadIdx.x;
    float a = fcb[f];
    #pragma unroll
    for (int c = 0; c < 8; c++) a = fmaf(g_pooled[z*8 + c], fcw[c*FF + f], a);
    g_h[z*FF + f] = softplus1(a);
}

// ---------------- 8. batch statistics -------------------------------------
__global__ void k_stats() {
    int f = threadIdx.x;
    float m = 0.0f;
    #pragma unroll
    for (int z = 0; z < BB; z++) m += g_h[z*FF + f];
    m *= (1.0f / (float)BB);
    float v = 0.0f;
    #pragma unroll
    for (int z = 0; z < BB; z++) { float d = g_h[z*FF + f] - m; v += d*d; }
    v *= (1.0f / (float)BB);
    g_mean[f] = m;
    g_var[f] = v;
}

// ---------------- 9. batchnorm + softplus + output head -------------------
__global__ void k_out(const float* __restrict__ bng, const float* __restrict__ bnb,
                      const float* __restrict__ ow, const float* __restrict__ ob,
                      float* __restrict__ out) {
    int z = blockIdx.x;
    int lane = threadIdx.x & 31, warp = threadIdx.x >> 5;
    float acc = 0.0f;
    for (int f = threadIdx.x; f < FF; f += blockDim.x) {
        float hv = g_h[z*FF + f];
        float hn = (hv - g_mean[f]) * rsqrtf(g_var[f] + 1e-5f) * bng[f] + bnb[f];
        acc += softplus1(hn) * ow[f];
    }
    for (int off = 16; off; off >>= 1) acc += __shfl_down_sync(0xffffffffu, acc, off);
    __shared__ float sm[8];
    if (lane == 0) sm[warp] = acc;
    __syncthreads();
    if (threadIdx.x == 0) {
        float t = 0.0f;
        #pragma unroll
        for (int w = 0; w < 8; w++) t += sm[w];
        t += ob[0];
        out[z] = 1.0f / (1.0f + expf(-t));
    }
}

// ---------------- launch --------------------------------------------------
extern "C" void kernel_launch(void* const* d_in, const int* in_sizes, int n_in,
                              void* d_out, int out_size) {
    const float* xyz   = (const float*)d_in[0];
    const int*   Z     = (const int*)  d_in[1];
    const float* emb   = (const float*)d_in[2];
    // c0: w0,b0,w1,b1,w2,b2,w3,b3 -> indices 3..10 ; c1 -> 11..18
    const float* c0_w0 = (const float*)d_in[3];
    const float* c0_b0 = (const float*)d_in[4];
    const float* c0_w1 = (const float*)d_in[5];
    const float* c0_b1 = (const float*)d_in[6];
    const float* c0_w2 = (const float*)d_in[7];
    const float* c0_b2 = (const float*)d_in[8];
    const float* c0_w3 = (const float*)d_in[9];
    const float* c0_b3 = (const float*)d_in[10];
    const float* c1_w0 = (const float*)d_in[11];
    const float* c1_b0 = (const float*)d_in[12];
    const float* c1_w1 = (const float*)d_in[13];
    const float* c1_b1 = (const float*)d_in[14];
    const float* c1_w2 = (const float*)d_in[15];
    const float* c1_b2 = (const float*)d_in[16];
    const float* c1_w3 = (const float*)d_in[17];
    const float* c1_b3 = (const float*)d_in[18];
    const float* fc_w  = (const float*)d_in[19];
    const float* fc_b  = (const float*)d_in[20];
    const float* bn_g  = (const float*)d_in[21];
    const float* bn_b  = (const float*)d_in[22];
    const float* out_w = (const float*)d_in[23];
    const float* out_b = (const float*)d_in[24];
    float* out = (float*)d_out;

    k_embed<<<(BB*NA + 255) / 256, 256>>>(Z, emb);
    k_pad<<<dim3((HID*HIDP + 255) / 256, 4), 256>>>(c0_w1, c0_w2, c1_w1, c1_w2);
    k_dist<<<BB*NA, 256>>>(xyz);

    BuildArgs ba;
    ba.c[0].w0 = c0_w0; ba.c[0].b0 = c0_b0; ba.c[0].b1 = c0_b1; ba.c[0].b2 = c0_b2;
    ba.c[0].w3 = c0_w3; ba.c[0].b3 = c0_b3;
    ba.c[1].w0 = c1_w0; ba.c[1].b0 = c1_b0; ba.c[1].b1 = c1_b1; ba.c[1].b2 = c1_b2;
    ba.c[1].w3 = c1_w3; ba.c[1].b3 = c1_b3;
    k_build<<<dim3(MT / (BW*PTW), 2), BW*32>>>(ba);

    k_conv<<<BB*NA, 256>>>(0);
    k_conv<<<BB*NA, 256>>>(1);
    k_pool<<<BB, 256>>>();
    k_fc<<<BB, FF>>>(fc_w, fc_b);
    k_stats<<<1, FF>>>();
    k_out<<<BB, 256>>>(bn_g, bn_b, out_w, out_b, out);
}

// round 5
// speedup vs baseline: 1.3237x; 1.3237x over previous
#include <cuda_runtime.h>
#include <math.h>

#define BB      16
#define NA      286
#define NPAIR   (NA*NA)
#define HID     150
#define HIDP    160
#define FF      512
#define RADIUS_F 3.0f
#define MT      512       // table knots per cloud
#define PTS     4         // points per build block

// ---------------- scratch (device globals; no allocation allowed) ----------
__device__ __align__(16) float g_feats0[BB*NA*4];
__device__ __align__(16) float g_f1[BB*NA*4];
__device__ __align__(16) float g_f2[BB*NA*4];
__device__ float g_dist[BB*NPAIR];
__device__ float g_nbinv[BB*NA];
__device__ __align__(16) float g_tab[2][MT*16];
__device__ float g_wpad[4][HID*HIDP];     // c0_w1, c0_w2, c1_w1, c1_w2 (padded rows of 160)
__device__ float g_pooled[BB*8];
__device__ float g_h[BB*FF];
__device__ float g_mean[FF];
__device__ float g_var[FF];

__device__ __forceinline__ float sp5(float x) {
    float z = 5.0f * x;
    return (fmaxf(z, 0.0f) + log1pf(expf(-fabsf(z)))) * 0.2f;
}
__device__ __forceinline__ float softplus1(float x) {
    return fmaxf(x, 0.0f) + log1pf(expf(-fabsf(x)));
}

// ---------------- 1. embedding gather -------------------------------------
__global__ void k_embed(const int* __restrict__ Z, const float* __restrict__ emb) {
    int i = blockIdx.x * blockDim.x + threadIdx.x;
    if (i < BB*NA) {
        int zi = Z[i];
        float4 e = *(const float4*)(emb + zi*4);
        *(float4*)(g_feats0 + i*4) = e;
    }
}

// ---------------- 2. pad mid-layer weights to 160-wide rows ---------------
__global__ void k_pad(const float* __restrict__ a, const float* __restrict__ b,
                      const float* __restrict__ c, const float* __restrict__ d) {
    const float* srcs[4] = {a, b, c, d};
    int m = blockIdx.y;
    const float* src = srcs[m];
    int i = blockIdx.x * blockDim.x + threadIdx.x;
    if (i < HID*HIDP) {
        int k = i / HIDP;
        int o = i - k*HIDP;
        g_wpad[m][i] = (o < HID) ? src[k*HID + o] : 0.0f;
    }
}

// ---------------- 3. pairwise distances + 1/sqrt(neighbor count) ----------
__global__ void k_dist(const float* __restrict__ xyz) {
    int za = blockIdx.x;
    int z = za / NA, a = za % NA;
    const float* pz = xyz + (size_t)z * NA * 3;
    float ax = pz[a*3+0], ay = pz[a*3+1], az = pz[a*3+2];
    int cnt = 0;
    for (int b = threadIdx.x; b < NA; b += blockDim.x) {
        float dx = ax - pz[b*3+0];
        float dy = ay - pz[b*3+1];
        float dz = az - pz[b*3+2];
        float d = sqrtf(dx*dx + dy*dy + dz*dz + 1e-12f);
        g_dist[(size_t)za*NA + b] = d;
        cnt += (d < RADIUS_F) ? 1 : 0;
    }
    for (int off = 16; off; off >>= 1) cnt += __shfl_down_sync(0xffffffffu, cnt, off);
    __shared__ int sc[8];
    int warp = threadIdx.x >> 5;
    if ((threadIdx.x & 31) == 0) sc[warp] = cnt;
    __syncthreads();
    if (threadIdx.x == 0) {
        int t = 0;
        for (int w = 0; w < (int)(blockDim.x >> 5); w++) t += sc[w];
        g_nbinv[za] = rsqrtf((float)max(t, 1));
    }
}

// ---------------- 4. radial-MLP table build (output-parallel) -------------
struct CloudW {
    const float* w0; const float* b0;
    const float* b1; const float* b2;
    const float* w3; const float* b3;
};
struct BuildArgs { CloudW c[2]; };

// Block: 160 threads (one per padded output column), PTS points per block.
// Activations live in shared (double-buffered). Inner loop = 1 coalesced LDG
// per k per thread (unroll 6 -> 6 loads in flight) + broadcast LDS + FMA.
__global__ void __launch_bounds__(HIDP) k_build(BuildArgs args) {
    int cloud = blockIdx.y;
    CloudW cw = args.c[cloud];
    int t = threadIdx.x;                 // 0..159
    int pt0 = blockIdx.x * PTS;

    __shared__ float Xs[2][PTS][HIDP];
    __shared__ float red[10][PTS][16];

    bool ok = (t < HID);

    // cosine basis at the PTS grid points (redundant per thread; cheap)
    float bas[PTS][3];
    const float hstep = RADIUS_F / (float)(MT - 1);
    #pragma unroll
    for (int p = 0; p < PTS; p++) {
        float r = (float)(pt0 + p) * hstep;
        #pragma unroll
        for (int j = 0; j < 3; j++) {
            float dd = (r - 1.5f * (float)j) * (1.0f / 1.5f);
            float cv = cosf(1.57079632679489662f * dd);
            bas[p][j] = (fabsf(dd) < 1.0f) ? cv * cv : 0.0f;
        }
    }

    // layer 0: 3 -> 150
    {
        float w0a = ok ? cw.w0[t]         : 0.0f;
        float w0b = ok ? cw.w0[HID + t]   : 0.0f;
        float w0c = ok ? cw.w0[2*HID + t] : 0.0f;
        float bb0 = ok ? cw.b0[t]         : 0.0f;
        #pragma unroll
        for (int p = 0; p < PTS; p++) {
            float av = bb0;
            av = fmaf(bas[p][0], w0a, av);
            av = fmaf(bas[p][1], w0b, av);
            av = fmaf(bas[p][2], w0c, av);
            Xs[0][p][t] = sp5(av);
        }
    }
    __syncthreads();

    // layers 1 & 2: 150 -> 150
    int cur = 0;
    #pragma unroll
    for (int L = 0; L < 2; ++L) {
        const float* wp = g_wpad[2*cloud + L];
        const float* bb = (L == 0) ? cw.b1 : cw.b2;
        float acc[PTS];
        float bv = ok ? bb[t] : 0.0f;
        #pragma unroll
        for (int p = 0; p < PTS; p++) acc[p] = bv;
        #pragma unroll 6
        for (int k = 0; k < HID; k++) {
            float w = wp[k*HIDP + t];
            #pragma unroll
            for (int p = 0; p < PTS; p++)
                acc[p] = fmaf(Xs[cur][p][k], w, acc[p]);
        }
        #pragma unroll
        for (int p = 0; p < PTS; p++) Xs[1 - cur][p][t] = sp5(acc[p]);
        cur ^= 1;
        __syncthreads();
    }

    // layer 3: 150 -> 16, split k across 10 chunks of 15 per output
    {
        int o = t & 15, c = t >> 4;      // c in 0..9
        float acc[PTS] = {0.f, 0.f, 0.f, 0.f};
        #pragma unroll
        for (int kk = 0; kk < 15; kk++) {
            int k = c*15 + kk;
            float w = cw.w3[k*16 + o];
            #pragma unroll
            for (int p = 0; p < PTS; p++)
                acc[p] = fmaf(Xs[cur][p][k], w, acc[p]);
        }
        #pragma unroll
        for (int p = 0; p < PTS; p++) red[c][p][o] = acc[p];
    }
    __syncthreads();
    if (t < 16*PTS) {
        int o = t & 15, p = t >> 4;
        float s = cw.b3[o];
        #pragma unroll
        for (int c = 0; c < 10; c++) s += red[c][p][o];
        g_tab[cloud][(pt0 + p)*16 + o] = s;
    }
}

// ---------------- 5. pair convolution (table interp + 4x4 matvec) ---------
__global__ void k_conv(int cloud) {
    int za = blockIdx.x;
    int z = za / NA;
    const float* feats = (cloud == 0) ? g_feats0 : g_f1;
    float* out         = (cloud == 0) ? g_f1     : g_f2;
    const float* tab   = g_tab[cloud];

    __shared__ float4 sf[NA];
    const float4* fz = (const float4*)(feats + (size_t)z * NA * 4);
    for (int b = threadIdx.x; b < NA; b += blockDim.x) sf[b] = fz[b];
    __syncthreads();

    const float* drow = g_dist + (size_t)za * NA;
    int lane = threadIdx.x & 31, warp = threadIdx.x >> 5;
    int q = lane & 3;        // output channel
    int p = lane >> 2;       // pair slot within warp (0..7)
    const float uscale = (float)(MT - 1) / RADIUS_F;

    float acc = 0.0f;
    for (int b = warp*8 + p; b < NA; b += 64) {
        float r = drow[b];
        if (r < RADIUS_F) {
            float u = r * uscale;
            int i0 = (int)u;
            i0 = min(i0, MT - 2);
            float t = u - (float)i0;
            const float4* rp = (const float4*)(tab + i0*16) + q;
            float4 k0 = rp[0];
            float4 k1 = rp[4];
            float kx = fmaf(t, k1.x - k0.x, k0.x);
            float ky = fmaf(t, k1.y - k0.y, k0.y);
            float kz = fmaf(t, k1.z - k0.z, k0.z);
            float kw = fmaf(t, k1.w - k0.w, k0.w);
            float4 f = sf[b];
            acc += kx*f.x + ky*f.y + kz*f.z + kw*f.w;
        }
    }
    acc += __shfl_down_sync(0xffffffffu, acc, 16);
    acc += __shfl_down_sync(0xffffffffu, acc, 8);
    acc += __shfl_down_sync(0xffffffffu, acc, 4);
    __shared__ float sr[8][4];
    if (lane < 4) sr[warp][q] = acc;
    __syncthreads();
    if (threadIdx.x < 4) {
        float s = 0.0f;
        #pragma unroll
        for (int w = 0; w < 8; w++) s += sr[w][threadIdx.x];
        out[(size_t)za*4 + threadIdx.x] = s * g_nbinv[za];
    }
}

// ---------------- 6. L2 pool over atoms -----------------------------------
__global__ void k_pool() {
    int z = blockIdx.x;
    int lane = threadIdx.x & 31, warp = threadIdx.x >> 5;
    float s[8] = {0,0,0,0,0,0,0,0};
    for (int a = threadIdx.x; a < NA; a += blockDim.x) {
        float4 f1 = *(const float4*)(g_f1 + ((size_t)z*NA + a)*4);
        float4 f2 = *(const float4*)(g_f2 + ((size_t)z*NA + a)*4);
        s[0] += f1.x*f1.x; s[1] += f1.y*f1.y; s[2] += f1.z*f1.z; s[3] += f1.w*f1.w;
        s[4] += f2.x*f2.x; s[5] += f2.y*f2.y; s[6] += f2.z*f2.z; s[7] += f2.w*f2.w;
    }
    #pragma unroll
    for (int j = 0; j < 8; j++)
        for (int off = 16; off; off >>= 1) s[j] += __shfl_down_sync(0xffffffffu, s[j], off);
    __shared__ float sm[8][8];
    if (lane == 0) {
        #pragma unroll
        for (int j = 0; j < 8; j++) sm[warp][j] = s[j];
    }
    __syncthreads();
    if (threadIdx.x < 8) {
        float t = 0.0f;
        #pragma unroll
        for (int w = 0; w < 8; w++) t += sm[w][threadIdx.x];
        g_pooled[z*8 + threadIdx.x] = sqrtf(t);
    }
}

// ---------------- 7. FC + softplus ----------------------------------------
__global__ void k_fc(const float* __restrict__ fcw, const float* __restrict__ fcb) {
    int z = blockIdx.x, f = threadIdx.x;
    float a = fcb[f];
    #pragma unroll
    for (int c = 0; c < 8; c++) a = fmaf(g_pooled[z*8 + c], fcw[c*FF + f], a);
    g_h[z*FF + f] = softplus1(a);
}

// ---------------- 8. batch statistics -------------------------------------
__global__ void k_stats() {
    int f = threadIdx.x;
    float m = 0.0f;
    #pragma unroll
    for (int z = 0; z < BB; z++) m += g_h[z*FF + f];
    m *= (1.0f / (float)BB);
    float v = 0.0f;
    #pragma unroll
    for (int z = 0; z < BB; z++) { float d = g_h[z*FF + f] - m; v += d*d; }
    v *= (1.0f / (float)BB);
    g_mean[f] = m;
    g_var[f] = v;
}

// ---------------- 9. batchnorm + softplus + output head -------------------
__global__ void k_out(const float* __restrict__ bng, const float* __restrict__ bnb,
                      const float* __restrict__ ow, const float* __restrict__ ob,
                      float* __restrict__ out) {
    int z = blockIdx.x;
    int lane = threadIdx.x & 31, warp = threadIdx.x >> 5;
    float acc = 0.0f;
    for (int f = threadIdx.x; f < FF; f += blockDim.x) {
        float hv = g_h[z*FF + f];
        float hn = (hv - g_mean[f]) * rsqrtf(g_var[f] + 1e-5f) * bng[f] + bnb[f];
        acc += softplus1(hn) * ow[f];
    }
    for (int off = 16; off; off >>= 1) acc += __shfl_down_sync(0xffffffffu, acc, off);
    __shared__ float sm[8];
    if (lane == 0) sm[warp] = acc;
    __syncthreads();
    if (threadIdx.x == 0) {
        float t = 0.0f;
        #pragma unroll
        for (int w = 0; w < 8; w++) t += sm[w];
        t += ob[0];
        out[z] = 1.0f / (1.0f + expf(-t));
    }
}

// ---------------- launch --------------------------------------------------
extern "C" void kernel_launch(void* const* d_in, const int* in_sizes, int n_in,
                              void* d_out, int out_size) {
    const float* xyz   = (const float*)d_in[0];
    const int*   Z     = (const int*)  d_in[1];
    const float* emb   = (const float*)d_in[2];
    const float* c0_w0 = (const float*)d_in[3];
    const float* c0_b0 = (const float*)d_in[4];
    const float* c0_w1 = (const float*)d_in[5];
    const float* c0_b1 = (const float*)d_in[6];
    const float* c0_w2 = (const float*)d_in[7];
    const float* c0_b2 = (const float*)d_in[8];
    const float* c0_w3 = (const float*)d_in[9];
    const float* c0_b3 = (const float*)d_in[10];
    const float* c1_w0 = (const float*)d_in[11];
    const float* c1_b0 = (const float*)d_in[12];
    const float* c1_w1 = (const float*)d_in[13];
    const float* c1_b1 = (const float*)d_in[14];
    const float* c1_w2 = (const float*)d_in[15];
    const float* c1_b2 = (const float*)d_in[16];
    const float* c1_w3 = (const float*)d_in[17];
    const float* c1_b3 = (const float*)d_in[18];
    const float* fc_w  = (const float*)d_in[19];
    const float* fc_b  = (const float*)d_in[20];
    const float* bn_g  = (const float*)d_in[21];
    const float* bn_b  = (const float*)d_in[22];
    const float* out_w = (const float*)d_in[23];
    const float* out_b = (const float*)d_in[24];
    float* out = (float*)d_out;

    k_embed<<<(BB*NA + 255) / 256, 256>>>(Z, emb);
    k_pad<<<dim3((HID*HIDP + 255) / 256, 4), 256>>>(c0_w1, c0_w2, c1_w1, c1_w2);
    k_dist<<<BB*NA, 256>>>(xyz);

    BuildArgs ba;
    ba.c[0].w0 = c0_w0; ba.c[0].b0 = c0_b0; ba.c[0].b1 = c0_b1; ba.c[0].b2 = c0_b2;
    ba.c[0].w3 = c0_w3; ba.c[0].b3 = c0_b3;
    ba.c[1].w0 = c1_w0; ba.c[1].b0 = c1_b0; ba.c[1].b1 = c1_b1; ba.c[1].b2 = c1_b2;
    ba.c[1].w3 = c1_w3; ba.c[1].b3 = c1_b3;
    k_build<<<dim3(MT / PTS, 2), HIDP>>>(ba);

    k_conv<<<BB*NA, 256>>>(0);
    k_conv<<<BB*NA, 256>>>(1);
    k_pool<<<BB, 256>>>();
    k_fc<<<BB, FF>>>(fc_w, fc_b);
    k_stats<<<1, FF>>>();
    k_out<<<BB, 256>>>(bn_g, bn_b, out_w, out_b, out);
}

// round 6
// speedup vs baseline: 2.1606x; 1.6322x over previous
#include <cuda_runtime.h>
#include <math.h>

#define BB      16
#define NA      286
#define HID     150
#define HIDP    160
#define FF      512
#define RADIUS_F 3.0f
#define MT      512       // table knots per cloud
#define PTS     4         // points per build block
#define CH      10        // k-chunk (prefetch depth) in build
#define ATILE   16        // atoms per conv block

// ---------------- scratch (device globals; no allocation allowed) ----------
__device__ __align__(16) float g_feats0[BB*NA*4];
__device__ __align__(16) float g_f1[BB*NA*4];
__device__ __align__(16) float g_f2[BB*NA*4];
__device__ __align__(16) float g_tab[2][MT*16];
__device__ float g_wpad[4][HID*HIDP];     // c0_w1, c0_w2, c1_w1, c1_w2 (160-wide rows)
__device__ float g_h[BB*FF];

__device__ __forceinline__ float sp5(float x) {
    float z = 5.0f * x;
    return (fmaxf(z, 0.0f) + log1pf(expf(-fabsf(z)))) * 0.2f;
}
__device__ __forceinline__ float softplus1(float x) {
    return fmaxf(x, 0.0f) + log1pf(expf(-fabsf(x)));
}

// ---------------- 1. fused embedding gather + weight padding --------------
__global__ void k_embed_pad(const int* __restrict__ Z, const float* __restrict__ emb,
                            const float* __restrict__ a, const float* __restrict__ b,
                            const float* __restrict__ c, const float* __restrict__ d) {
    int m = blockIdx.y;
    int i = blockIdx.x * blockDim.x + threadIdx.x;
    if (m < 4) {
        const float* srcs[4] = {a, b, c, d};
        const float* src = srcs[m];
        if (i < HID*HIDP) {
            int k = i / HIDP;
            int o = i - k*HIDP;
            g_wpad[m][i] = (o < HID) ? src[k*HID + o] : 0.0f;
        }
    } else {
        if (i < BB*NA) {
            int zi = Z[i];
            float4 e = *(const float4*)(emb + zi*4);
            *(float4*)(g_feats0 + i*4) = e;
        }
    }
}

// ---------------- 2. radial-MLP table build (output-parallel, prefetched) --
struct CloudW {
    const float* w0; const float* b0;
    const float* b1; const float* b2;
    const float* w3; const float* b3;
};
struct BuildArgs { CloudW c[2]; };

__global__ void __launch_bounds__(HIDP) k_build(BuildArgs args) {
    int cloud = blockIdx.y;
    CloudW cw = args.c[cloud];
    int t = threadIdx.x;                 // 0..159
    int pt0 = blockIdx.x * PTS;

    // transposed activations: X[k] = (p0,p1,p2,p3) for feature k
    __shared__ float4 X0[HIDP];
    __shared__ float4 X1[HIDP];
    __shared__ float red[10][PTS][16];

    bool ok = (t < HID);

    // cosine basis at the PTS grid points
    float bas[PTS][3];
    const float hstep = RADIUS_F / (float)(MT - 1);
    #pragma unroll
    for (int p = 0; p < PTS; p++) {
        float r = (float)(pt0 + p) * hstep;
        #pragma unroll
        for (int j = 0; j < 3; j++) {
            float dd = (r - 1.5f * (float)j) * (1.0f / 1.5f);
            float cv = cosf(1.57079632679489662f * dd);
            bas[p][j] = (fabsf(dd) < 1.0f) ? cv * cv : 0.0f;
        }
    }

    // layer 0: 3 -> 150
    {
        float w0a = ok ? cw.w0[t]         : 0.0f;
        float w0b = ok ? cw.w0[HID + t]   : 0.0f;
        float w0c = ok ? cw.w0[2*HID + t] : 0.0f;
        float bb0 = ok ? cw.b0[t]         : 0.0f;
        float4 v;
        float* vp = (float*)&v;
        #pragma unroll
        for (int p = 0; p < PTS; p++) {
            float av = bb0;
            av = fmaf(bas[p][0], w0a, av);
            av = fmaf(bas[p][1], w0b, av);
            av = fmaf(bas[p][2], w0c, av);
            vp[p] = sp5(av);
        }
        X0[t] = v;
    }
    __syncthreads();

    // layers 1 & 2: 150 -> 150, register-prefetched weight chunks
    #pragma unroll
    for (int L = 0; L < 2; ++L) {
        const float* wp = g_wpad[2*cloud + L];
        const float* bb = (L == 0) ? cw.b1 : cw.b2;
        const float4* S = (L == 0) ? X0 : X1;
        float4*       D = (L == 0) ? X1 : X0;

        float bv = ok ? bb[t] : 0.0f;
        float acc0 = bv, acc1 = bv, acc2 = bv, acc3 = bv;

        float wbuf[CH];
        #pragma unroll
        for (int j = 0; j < CH; j++) wbuf[j] = wp[j*HIDP + t];

        for (int k0 = 0; k0 < HID; k0 += CH) {   // 15 chunks
            float wn[CH];
            bool more = (k0 + CH < HID);
            #pragma unroll
            for (int j = 0; j < CH; j++)
                wn[j] = more ? wp[(k0 + CH + j)*HIDP + t] : 0.0f;
            #pragma unroll
            for (int j = 0; j < CH; j++) {
                float4 x = S[k0 + j];
                acc0 = fmaf(x.x, wbuf[j], acc0);
                acc1 = fmaf(x.y, wbuf[j], acc1);
                acc2 = fmaf(x.z, wbuf[j], acc2);
                acc3 = fmaf(x.w, wbuf[j], acc3);
            }
            #pragma unroll
            for (int j = 0; j < CH; j++) wbuf[j] = wn[j];
        }
        float4 dv;
        dv.x = sp5(acc0); dv.y = sp5(acc1); dv.z = sp5(acc2); dv.w = sp5(acc3);
        D[t] = dv;
        __syncthreads();
    }

    // layer 3: 150 -> 16, split k across 10 chunks of 15 (source is X0)
    {
        int o = t & 15, c = t >> 4;      // c in 0..9
        float a0 = 0.f, a1 = 0.f, a2 = 0.f, a3 = 0.f;
        #pragma unroll
        for (int kk = 0; kk < 15; kk++) {
            int k = c*15 + kk;
            float w = cw.w3[k*16 + o];
            float4 x = X0[k];
            a0 = fmaf(x.x, w, a0);
            a1 = fmaf(x.y, w, a1);
            a2 = fmaf(x.z, w, a2);
            a3 = fmaf(x.w, w, a3);
        }
        red[c][0][o] = a0; red[c][1][o] = a1;
        red[c][2][o] = a2; red[c][3][o] = a3;
    }
    __syncthreads();
    if (t < 16*PTS) {
        int o = t & 15, p = t >> 4;
        float s = cw.b3[o];
        #pragma unroll
        for (int c = 0; c < 10; c++) s += red[c][p][o];
        g_tab[cloud][(pt0 + p)*16 + o] = s;
    }
}

// ---------------- 3. pair convolution (inline dist + table interp) --------
// grid (ceil(NA/ATILE), BB), 256 threads. Each warp handles 2 atoms.
// Within a warp: lane = 4 channels (q) x 8 pair slots (p).
__global__ void __launch_bounds__(256) k_conv(const float* __restrict__ xyz, int cloud) {
    int z  = blockIdx.y;
    int a0 = blockIdx.x * ATILE;
    const float* feats = cloud ? g_f1 : g_feats0;
    float*       out   = cloud ? g_f2 : g_f1;
    const float* tab   = g_tab[cloud];

    __shared__ float sx[NA], sy[NA], sz[NA];
    __shared__ float4 sf[NA];
    const float*  xr = xyz + (size_t)z * NA * 3;
    const float4* fz = (const float4*)(feats + (size_t)z * NA * 4);
    for (int i = threadIdx.x; i < NA; i += 256) {
        sx[i] = xr[i*3+0];
        sy[i] = xr[i*3+1];
        sz[i] = xr[i*3+2];
        sf[i] = fz[i];
    }
    __syncthreads();

    int warp = threadIdx.x >> 5, lane = threadIdx.x & 31;
    int q = lane & 3;        // output channel
    int p = lane >> 2;       // pair slot (0..7)
    const float uscale = (float)(MT - 1) / RADIUS_F;

    #pragma unroll
    for (int j = 0; j < 2; j++) {
        int a = a0 + warp + 8*j;
        bool valid = (a < NA);
        float acc = 0.0f;
        int cnt = 0;
        if (valid) {
            float ax = sx[a], ay = sy[a], az = sz[a];
            for (int b = p; b < NA; b += 8) {
                float dx = ax - sx[b];
                float dy = ay - sy[b];
                float dz = az - sz[b];
                float d2 = dx*dx + dy*dy + dz*dz;
                if (d2 < 9.0f) {
                    cnt++;
                    float d = sqrtf(d2 + 1e-12f);
                    float u = d * uscale;
                    int i0 = (int)u;
                    i0 = min(i0, MT - 2);
                    float tt = u - (float)i0;
                    const float4* rp = (const float4*)(tab + i0*16) + q;
                    float4 k0 = rp[0];
                    float4 k1 = rp[4];
                    float4 f = sf[b];
                    float kx = fmaf(tt, k1.x - k0.x, k0.x);
                    float ky = fmaf(tt, k1.y - k0.y, k0.y);
                    float kz = fmaf(tt, k1.z - k0.z, k0.z);
                    float kw = fmaf(tt, k1.w - k0.w, k0.w);
                    acc += kx*f.x + ky*f.y + kz*f.z + kw*f.w;
                }
            }
        }
        // reduce over the 8 pair slots (lanes differing in bits 2..4)
        acc += __shfl_down_sync(0xffffffffu, acc, 16);
        acc += __shfl_down_sync(0xffffffffu, acc, 8);
        acc += __shfl_down_sync(0xffffffffu, acc, 4);
        cnt += __shfl_down_sync(0xffffffffu, cnt, 16);
        cnt += __shfl_down_sync(0xffffffffu, cnt, 8);
        cnt += __shfl_down_sync(0xffffffffu, cnt, 4);
        if (valid && lane < 4)
            out[((size_t)z*NA + a)*4 + lane] = acc * rsqrtf((float)max(cnt, 1));
    }
}

// ---------------- 4. fused L2-pool + FC + softplus ------------------------
__global__ void __launch_bounds__(FF) k_poolfc(const float* __restrict__ fcw,
                                               const float* __restrict__ fcb) {
    int z = blockIdx.x;
    int lane = threadIdx.x & 31, warp = threadIdx.x >> 5;
    __shared__ float sm[16][8];
    __shared__ float spool[8];

    float s[8] = {0,0,0,0,0,0,0,0};
    for (int a = threadIdx.x; a < NA; a += FF) {
        float4 f1 = *(const float4*)(g_f1 + ((size_t)z*NA + a)*4);
        float4 f2 = *(const float4*)(g_f2 + ((size_t)z*NA + a)*4);
        s[0] += f1.x*f1.x; s[1] += f1.y*f1.y; s[2] += f1.z*f1.z; s[3] += f1.w*f1.w;
        s[4] += f2.x*f2.x; s[5] += f2.y*f2.y; s[6] += f2.z*f2.z; s[7] += f2.w*f2.w;
    }
    #pragma unroll
    for (int j = 0; j < 8; j++)
        for (int off = 16; off; off >>= 1) s[j] += __shfl_down_sync(0xffffffffu, s[j], off);
    if (lane == 0) {
        #pragma unroll
        for (int j = 0; j < 8; j++) sm[warp][j] = s[j];
    }
    __syncthreads();
    if (threadIdx.x < 8) {
        float t = 0.0f;
        #pragma unroll
        for (int w = 0; w < 16; w++) t += sm[w][threadIdx.x];
        spool[threadIdx.x] = sqrtf(t);
    }
    __syncthreads();
    int f = threadIdx.x;
    float a = fcb[f];
    #pragma unroll
    for (int c = 0; c < 8; c++) a = fmaf(spool[c], fcw[c*FF + f], a);
    g_h[z*FF + f] = softplus1(a);
}

// ---------------- 5. fused batch-stats + batchnorm + output head ----------
__global__ void __launch_bounds__(FF) k_statsout(const float* __restrict__ bng,
                                                 const float* __restrict__ bnb,
                                                 const float* __restrict__ ow,
                                                 const float* __restrict__ ob,
                                                 float* __restrict__ out) {
    int f = threadIdx.x;
    int lane = f & 31, warp = f >> 5;
    __shared__ float smw[16][BB];

    float hv[BB];
    float m = 0.0f;
    #pragma unroll
    for (int z = 0; z < BB; z++) { hv[z] = g_h[z*FF + f]; m += hv[z]; }
    m *= (1.0f / (float)BB);
    float v = 0.0f;
    #pragma unroll
    for (int z = 0; z < BB; z++) { float d = hv[z] - m; v += d*d; }
    v *= (1.0f / (float)BB);
    float sc = rsqrtf(v + 1e-5f) * bng[f];
    float bo = bnb[f];
    float w  = ow[f];

    float acc[BB];
    #pragma unroll
    for (int z = 0; z < BB; z++)
        acc[z] = softplus1((hv[z] - m) * sc + bo) * w;

    #pragma unroll
    for (int z = 0; z < BB; z++)
        for (int off = 16; off; off >>= 1)
            acc[z] += __shfl_down_sync(0xffffffffu, acc[z], off);
    if (lane == 0) {
        #pragma unroll
        for (int z = 0; z < BB; z++) smw[warp][z] = acc[z];
    }
    __syncthreads();
    if (f < BB) {
        float t = ob[0];
        #pragma unroll
        for (int wI = 0; wI < 16; wI++) t += smw[wI][f];
        out[f] = 1.0f / (1.0f + expf(-t));
    }
}

// ---------------- launch --------------------------------------------------
extern "C" void kernel_launch(void* const* d_in, const int* in_sizes, int n_in,
                              void* d_out, int out_size) {
    const float* xyz   = (const float*)d_in[0];
    const int*   Z     = (const int*)  d_in[1];
    const float* emb   = (const float*)d_in[2];
    const float* c0_w0 = (const float*)d_in[3];
    const float* c0_b0 = (const float*)d_in[4];
    const float* c0_w1 = (const float*)d_in[5];
    const float* c0_b1 = (const float*)d_in[6];
    const float* c0_w2 = (const float*)d_in[7];
    const float* c0_b2 = (const float*)d_in[8];
    const float* c0_w3 = (const float*)d_in[9];
    const float* c0_b3 = (const float*)d_in[10];
    const float* c1_w0 = (const float*)d_in[11];
    const float* c1_b0 = (const float*)d_in[12];
    const float* c1_w1 = (const float*)d_in[13];
    const float* c1_b1 = (const float*)d_in[14];
    const float* c1_w2 = (const float*)d_in[15];
    const float* c1_b2 = (const float*)d_in[16];
    const float* c1_w3 = (const float*)d_in[17];
    const float* c1_b3 = (const float*)d_in[18];
    const float* fc_w  = (const float*)d_in[19];
    const float* fc_b  = (const float*)d_in[20];
    const float* bn_g  = (const float*)d_in[21];
    const float* bn_b  = (const float*)d_in[22];
    const float* out_w = (const float*)d_in[23];
    const float* out_b = (const float*)d_in[24];
    float* out = (float*)d_out;

    k_embed_pad<<<dim3((HID*HIDP + 255) / 256, 5), 256>>>(Z, emb, c0_w1, c0_w2, c1_w1, c1_w2);

    BuildArgs ba;
    ba.c[0].w0 = c0_w0; ba.c[0].b0 = c0_b0; ba.c[0].b1 = c0_b1; ba.c[0].b2 = c0_b2;
    ba.c[0].w3 = c0_w3; ba.c[0].b3 = c0_b3;
    ba.c[1].w0 = c1_w0; ba.c[1].b0 = c1_b0; ba.c[1].b1 = c1_b1; ba.c[1].b2 = c1_b2;
    ba.c[1].w3 = c1_w3; ba.c[1].b3 = c1_b3;
    k_build<<<dim3(MT / PTS, 2), HIDP>>>(ba);

    dim3 cg((NA + ATILE - 1) / ATILE, BB);
    k_conv<<<cg, 256>>>(xyz, 0);
    k_conv<<<cg, 256>>>(xyz, 1);
    k_poolfc<<<BB, FF>>>(fc_w, fc_b);
    k_statsout<<<1, FF>>>(bn_g, bn_b, out_w, out_b, out);
}

// round 7
// speedup vs baseline: 2.6711x; 1.2363x over previous
#include <cuda_runtime.h>
#include <math.h>

#define BB      16
#define NA      286
#define NAP     288       // padded atom count (multiple of 8)
#define HID     150
#define HIDP    160
#define FF      512
#define RADIUS_F 3.0f
#define MT      512       // table knots per cloud
#define PTS     4         // points per build block
#define CH      10        // k-chunk (prefetch depth) in build
#define ATILE   8         // atoms per conv block (1 per warp)

// ---------------- scratch (device globals; no allocation allowed) ----------
__device__ __align__(16) float g_feats0[BB*NA*4];
__device__ __align__(16) float g_f1[BB*NA*4];
__device__ __align__(16) float g_f2[BB*NA*4];
__device__ __align__(16) float g_tab[2][MT*16];
__device__ float g_wpad[4][HID*HIDP];     // c0_w1, c0_w2, c1_w1, c1_w2 (160-wide rows)
__device__ float g_h[BB*FF];

__device__ __forceinline__ float sp5(float x) {
    float z = 5.0f * x;
    return (fmaxf(z, 0.0f) + log1pf(expf(-fabsf(z)))) * 0.2f;
}
__device__ __forceinline__ float softplus1(float x) {
    return fmaxf(x, 0.0f) + log1pf(expf(-fabsf(x)));
}

// ---------------- 1. fused embedding gather + weight padding --------------
__global__ void k_embed_pad(const int* __restrict__ Z, const float* __restrict__ emb,
                            const float* __restrict__ a, const float* __restrict__ b,
                            const float* __restrict__ c, const float* __restrict__ d) {
    int m = blockIdx.y;
    int i = blockIdx.x * blockDim.x + threadIdx.x;
    if (m < 4) {
        const float* srcs[4] = {a, b, c, d};
        const float* src = srcs[m];
        if (i < HID*HIDP) {
            int k = i / HIDP;
            int o = i - k*HIDP;
            g_wpad[m][i] = (o < HID) ? src[k*HID + o] : 0.0f;
        }
    } else {
        if (i < BB*NA) {
            int zi = Z[i];
            float4 e = *(const float4*)(emb + zi*4);
            *(float4*)(g_feats0 + i*4) = e;
        }
    }
}

// ---------------- 2. radial-MLP table build (output-parallel, prefetched) --
struct CloudW {
    const float* w0; const float* b0;
    const float* b1; const float* b2;
    const float* w3; const float* b3;
};
struct BuildArgs { CloudW c[2]; };

__global__ void __launch_bounds__(HIDP) k_build(BuildArgs args) {
    int cloud = blockIdx.y;
    CloudW cw = args.c[cloud];
    int t = threadIdx.x;                 // 0..159
    int pt0 = blockIdx.x * PTS;

    __shared__ float4 X0[HIDP];
    __shared__ float4 X1[HIDP];
    __shared__ float red[10][PTS][16];

    bool ok = (t < HID);

    float bas[PTS][3];
    const float hstep = RADIUS_F / (float)(MT - 1);
    #pragma unroll
    for (int p = 0; p < PTS; p++) {
        float r = (float)(pt0 + p) * hstep;
        #pragma unroll
        for (int j = 0; j < 3; j++) {
            float dd = (r - 1.5f * (float)j) * (1.0f / 1.5f);
            float cv = cosf(1.57079632679489662f * dd);
            bas[p][j] = (fabsf(dd) < 1.0f) ? cv * cv : 0.0f;
        }
    }

    // layer 0: 3 -> 150
    {
        float w0a = ok ? cw.w0[t]         : 0.0f;
        float w0b = ok ? cw.w0[HID + t]   : 0.0f;
        float w0c = ok ? cw.w0[2*HID + t] : 0.0f;
        float bb0 = ok ? cw.b0[t]         : 0.0f;
        float4 v;
        float* vp = (float*)&v;
        #pragma unroll
        for (int p = 0; p < PTS; p++) {
            float av = bb0;
            av = fmaf(bas[p][0], w0a, av);
            av = fmaf(bas[p][1], w0b, av);
            av = fmaf(bas[p][2], w0c, av);
            vp[p] = sp5(av);
        }
        X0[t] = v;
    }
    __syncthreads();

    // layers 1 & 2: 150 -> 150, register-prefetched weight chunks
    #pragma unroll
    for (int L = 0; L < 2; ++L) {
        const float* wp = g_wpad[2*cloud + L];
        const float* bb = (L == 0) ? cw.b1 : cw.b2;
        const float4* S = (L == 0) ? X0 : X1;
        float4*       D = (L == 0) ? X1 : X0;

        float bv = ok ? bb[t] : 0.0f;
        float acc0 = bv, acc1 = bv, acc2 = bv, acc3 = bv;

        float wbuf[CH];
        #pragma unroll
        for (int j = 0; j < CH; j++) wbuf[j] = wp[j*HIDP + t];

        for (int k0 = 0; k0 < HID; k0 += CH) {   // 15 chunks
            float wn[CH];
            bool more = (k0 + CH < HID);
            #pragma unroll
            for (int j = 0; j < CH; j++)
                wn[j] = more ? wp[(k0 + CH + j)*HIDP + t] : 0.0f;
            #pragma unroll
            for (int j = 0; j < CH; j++) {
                float4 x = S[k0 + j];
                acc0 = fmaf(x.x, wbuf[j], acc0);
                acc1 = fmaf(x.y, wbuf[j], acc1);
                acc2 = fmaf(x.z, wbuf[j], acc2);
                acc3 = fmaf(x.w, wbuf[j], acc3);
            }
            #pragma unroll
            for (int j = 0; j < CH; j++) wbuf[j] = wn[j];
        }
        float4 dv;
        dv.x = sp5(acc0); dv.y = sp5(acc1); dv.z = sp5(acc2); dv.w = sp5(acc3);
        D[t] = dv;
        __syncthreads();
    }

    // layer 3: 150 -> 16, split k across 10 chunks of 15 (source is X0)
    {
        int o = t & 15, c = t >> 4;
        float a0 = 0.f, a1 = 0.f, a2 = 0.f, a3 = 0.f;
        #pragma unroll
        for (int kk = 0; kk < 15; kk++) {
            int k = c*15 + kk;
            float w = cw.w3[k*16 + o];
            float4 x = X0[k];
            a0 = fmaf(x.x, w, a0);
            a1 = fmaf(x.y, w, a1);
            a2 = fmaf(x.z, w, a2);
            a3 = fmaf(x.w, w, a3);
        }
        red[c][0][o] = a0; red[c][1][o] = a1;
        red[c][2][o] = a2; red[c][3][o] = a3;
    }
    __syncthreads();
    if (t < 16*PTS) {
        int o = t & 15, p = t >> 4;
        float s = cw.b3[o];
        #pragma unroll
        for (int c = 0; c < 10; c++) s += red[c][p][o];
        g_tab[cloud][(pt0 + p)*16 + o] = s;
    }
}

// ---------------- 3. pair convolution (inline dist + table interp) --------
// grid (NAP/ATILE, BB), 256 threads, 1 atom per warp.
// Lane = 4 channels (q) x 8 pair slots (p). Padded smem, fixed 36-iter loop.
__global__ void __launch_bounds__(256) k_conv(const float* __restrict__ xyz, int cloud) {
    int z = blockIdx.y;
    const float* feats = cloud ? g_f1 : g_feats0;
    float*       out   = cloud ? g_f2 : g_f1;
    const float* tab   = g_tab[cloud];

    __shared__ float sx[NAP], sy[NAP], sz[NAP];
    __shared__ float4 sf[NAP];
    const float*  xr = xyz + (size_t)z * NA * 3;
    const float4* fz = (const float4*)(feats + (size_t)z * NA * 4);
    for (int i = threadIdx.x; i < NAP; i += 256) {
        bool real = (i < NA);
        sx[i] = real ? xr[i*3+0] : 1.0e6f;
        sy[i] = real ? xr[i*3+1] : 1.0e6f;
        sz[i] = real ? xr[i*3+2] : 1.0e6f;
        sf[i] = real ? fz[i] : make_float4(0.f, 0.f, 0.f, 0.f);
    }
    __syncthreads();

    int warp = threadIdx.x >> 5, lane = threadIdx.x & 31;
    int q = lane & 3;        // output channel
    int p = lane >> 2;       // pair slot (0..7)
    const float uscale = (float)(MT - 1) / RADIUS_F;

    int a = blockIdx.x * ATILE + warp;
    float ax = sx[a], ay = sy[a], az = sz[a];
    const float4* tq = (const float4*)tab + q;

    float acc = 0.0f;
    int cnt = 0;
    #pragma unroll 4
    for (int it = 0; it < NAP/8; it++) {
        int b = p + it*8;
        float dx = ax - sx[b];
        float dy = ay - sy[b];
        float dz = az - sz[b];
        float d2 = dx*dx + dy*dy + dz*dz;
        if (d2 < 9.0f) {
            cnt++;
            float d = sqrtf(d2 + 1e-12f);
            float u = d * uscale;
            int i0 = (int)u;
            i0 = min(i0, MT - 2);
            float tt = u - (float)i0;
            float4 k0 = tq[i0*4];
            float4 k1 = tq[i0*4 + 4];
            float4 f = sf[b];
            float kx = fmaf(tt, k1.x - k0.x, k0.x);
            float ky = fmaf(tt, k1.y - k0.y, k0.y);
            float kz = fmaf(tt, k1.z - k0.z, k0.z);
            float kw = fmaf(tt, k1.w - k0.w, k0.w);
            acc += kx*f.x + ky*f.y + kz*f.z + kw*f.w;
        }
    }
    // reduce over the 8 pair slots (lanes differing in bits 2..4)
    acc += __shfl_down_sync(0xffffffffu, acc, 16);
    acc += __shfl_down_sync(0xffffffffu, acc, 8);
    acc += __shfl_down_sync(0xffffffffu, acc, 4);
    cnt += __shfl_down_sync(0xffffffffu, cnt, 16);
    cnt += __shfl_down_sync(0xffffffffu, cnt, 8);
    cnt += __shfl_down_sync(0xffffffffu, cnt, 4);
    if (a < NA && lane < 4)
        out[((size_t)z*NA + a)*4 + lane] = acc * rsqrtf((float)max(cnt, 1));
}

// ---------------- 4. fused L2-pool + FC + softplus ------------------------
__global__ void __launch_bounds__(FF) k_poolfc(const float* __restrict__ fcw,
                                               const float* __restrict__ fcb) {
    int z = blockIdx.x;
    int lane = threadIdx.x & 31, warp = threadIdx.x >> 5;
    __shared__ float sm[16][8];
    __shared__ float spool[8];

    float s[8] = {0,0,0,0,0,0,0,0};
    for (int a = threadIdx.x; a < NA; a += FF) {
        float4 f1 = *(const float4*)(g_f1 + ((size_t)z*NA + a)*4);
        float4 f2 = *(const float4*)(g_f2 + ((size_t)z*NA + a)*4);
        s[0] += f1.x*f1.x; s[1] += f1.y*f1.y; s[2] += f1.z*f1.z; s[3] += f1.w*f1.w;
        s[4] += f2.x*f2.x; s[5] += f2.y*f2.y; s[6] += f2.z*f2.z; s[7] += f2.w*f2.w;
    }
    #pragma unroll
    for (int j = 0; j < 8; j++)
        for (int off = 16; off; off >>= 1) s[j] += __shfl_down_sync(0xffffffffu, s[j], off);
    if (lane == 0) {
        #pragma unroll
        for (int j = 0; j < 8; j++) sm[warp][j] = s[j];
    }
    __syncthreads();
    if (threadIdx.x < 8) {
        float t = 0.0f;
        #pragma unroll
        for (int w = 0; w < 16; w++) t += sm[w][threadIdx.x];
        spool[threadIdx.x] = sqrtf(t);
    }
    __syncthreads();
    int f = threadIdx.x;
    float a = fcb[f];
    #pragma unroll
    for (int c = 0; c < 8; c++) a = fmaf(spool[c], fcw[c*FF + f], a);
    g_h[z*FF + f] = softplus1(a);
}

// ---------------- 5. fused batch-stats + batchnorm + output head ----------
__global__ void __launch_bounds__(FF) k_statsout(const float* __restrict__ bng,
                                                 const float* __restrict__ bnb,
                                                 const float* __restrict__ ow,
                                                 const float* __restrict__ ob,
                                                 float* __restrict__ out) {
    int f = threadIdx.x;
    int lane = f & 31, warp = f >> 5;
    __shared__ float smw[16][BB];

    float hv[BB];
    float m = 0.0f;
    #pragma unroll
    for (int z = 0; z < BB; z++) { hv[z] = g_h[z*FF + f]; m += hv[z]; }
    m *= (1.0f / (float)BB);
    float v = 0.0f;
    #pragma unroll
    for (int z = 0; z < BB; z++) { float d = hv[z] - m; v += d*d; }
    v *= (1.0f / (float)BB);
    float sc = rsqrtf(v + 1e-5f) * bng[f];
    float bo = bnb[f];
    float w  = ow[f];

    float acc[BB];
    #pragma unroll
    for (int z = 0; z < BB; z++)
        acc[z] = softplus1((hv[z] - m) * sc + bo) * w;

    #pragma unroll
    for (int z = 0; z < BB; z++)
        for (int off = 16; off; off >>= 1)
            acc[z] += __shfl_down_sync(0xffffffffu, acc[z], off);
    if (lane == 0) {
        #pragma unroll
        for (int z = 0; z < BB; z++) smw[warp][z] = acc[z];
    }
    __syncthreads();
    if (f < BB) {
        float t = ob[0];
        #pragma unroll
        for (int wI = 0; wI < 16; wI++) t += smw[wI][f];
        out[f] = 1.0f / (1.0f + expf(-t));
    }
}

// ---------------- launch --------------------------------------------------
extern "C" void kernel_launch(void* const* d_in, const int* in_sizes, int n_in,
                              void* d_out, int out_size) {
    const float* xyz   = (const float*)d_in[0];
    const int*   Z     = (const int*)  d_in[1];
    const float* emb   = (const float*)d_in[2];
    const float* c0_w0 = (const float*)d_in[3];
    const float* c0_b0 = (const float*)d_in[4];
    const float* c0_w1 = (const float*)d_in[5];
    const float* c0_b1 = (const float*)d_in[6];
    const float* c0_w2 = (const float*)d_in[7];
    const float* c0_b2 = (const float*)d_in[8];
    const float* c0_w3 = (const float*)d_in[9];
    const float* c0_b3 = (const float*)d_in[10];
    const float* c1_w0 = (const float*)d_in[11];
    const float* c1_b0 = (const float*)d_in[12];
    const float* c1_w1 = (const float*)d_in[13];
    const float* c1_b1 = (const float*)d_in[14];
    const float* c1_w2 = (const float*)d_in[15];
    const float* c1_b2 = (const float*)d_in[16];
    const float* c1_w3 = (const float*)d_in[17];
    const float* c1_b3 = (const float*)d_in[18];
    const float* fc_w  = (const float*)d_in[19];
    const float* fc_b  = (const float*)d_in[20];
    const float* bn_g  = (const float*)d_in[21];
    const float* bn_b  = (const float*)d_in[22];
    const float* out_w = (const float*)d_in[23];
    const float* out_b = (const float*)d_in[24];
    float* out = (float*)d_out;

    k_embed_pad<<<dim3((HID*HIDP + 255) / 256, 5), 256>>>(Z, emb, c0_w1, c0_w2, c1_w1, c1_w2);

    BuildArgs ba;
    ba.c[0].w0 = c0_w0; ba.c[0].b0 = c0_b0; ba.c[0].b1 = c0_b1; ba.c[0].b2 = c0_b2;
    ba.c[0].w3 = c0_w3; ba.c[0].b3 = c0_b3;
    ba.c[1].w0 = c1_w0; ba.c[1].b0 = c1_b0; ba.c[1].b1 = c1_b1; ba.c[1].b2 = c1_b2;
    ba.c[1].w3 = c1_w3; ba.c[1].b3 = c1_b3;
    k_build<<<dim3(MT / PTS, 2), HIDP>>>(ba);

    dim3 cg(NAP / ATILE, BB);
    k_conv<<<cg, 256>>>(xyz, 0);
    k_conv<<<cg, 256>>>(xyz, 1);
    k_poolfc<<<BB, FF>>>(fc_w, fc_b);
    k_statsout<<<1, FF>>>(bn_g, bn_b, out_w, out_b, out);
}